// round 11
// baseline (speedup 1.0000x reference)
#include <cuda_runtime.h>

#define D    64
#define D4   16
#define RK   16
#define MAXN 100000
#define NBLK 592

typedef unsigned long long ull;

// Scratch (allocation-free rule: __device__ globals).
// g_AS : per node, 32 float4: pair-interleaved [Asrc(lane), Abh(lane)] x16
// g_Adst: per node, 16 float4: Adst row
// g_S  : per node, 32 float4: pair-interleaved [Ss(lane), Sh(lane)] x16
static __device__ __align__(32) float4 g_AS  [(size_t)MAXN * 32];
static __device__ __align__(32) float4 g_Adst[(size_t)MAXN * D4];
static __device__ __align__(32) float4 g_S   [(size_t)MAXN * 32];

// sigmoid via HW tanh: sigmoid(x) = 0.5*tanh(0.5x) + 0.5
__device__ __forceinline__ float sigm(float x) {
    float t;
    asm("tanh.approx.f32 %0, %1;" : "=f"(t) : "f"(0.5f * x));
    return fmaf(0.5f, t, 0.5f);
}
__device__ __forceinline__ void red_add_v4(float4* p, float4 v) {
    asm volatile("red.global.add.v4.f32 [%0], {%1,%2,%3,%4};"
                 :: "l"(p), "f"(v.x), "f"(v.y), "f"(v.z), "f"(v.w) : "memory");
}
// packed fp32x2 helpers (sm_100+)
__device__ __forceinline__ ull pk2(float lo, float hi) {
    ull r; asm("mov.b64 %0,{%1,%2};" : "=l"(r) : "f"(lo), "f"(hi)); return r;
}
__device__ __forceinline__ void upk2(ull v, float& lo, float& hi) {
    asm("mov.b64 {%0,%1},%2;" : "=f"(lo), "=f"(hi) : "l"(v));
}
__device__ __forceinline__ ull fma2(ull a, ull b, ull c) {
    ull d; asm("fma.rn.f32x2 %0,%1,%2,%3;" : "=l"(d) : "l"(a), "l"(b), "l"(c)); return d;
}
__device__ __forceinline__ ull add2(ull a, ull b) {
    ull d; asm("add.rn.f32x2 %0,%1,%2;" : "=l"(d) : "l"(a), "l"(b)); return d;
}

// ---- Blackwell 256-bit global accesses ----
__device__ __forceinline__ void ldg256(const float4* p, float4& a, float4& b) {
    asm("ld.global.v8.f32 {%0,%1,%2,%3,%4,%5,%6,%7}, [%8];"
        : "=f"(a.x), "=f"(a.y), "=f"(a.z), "=f"(a.w),
          "=f"(b.x), "=f"(b.y), "=f"(b.z), "=f"(b.w)
        : "l"(p));
}
__device__ __forceinline__ void stg256(float4* p, float4 a, float4 b) {
    asm volatile("st.global.v8.f32 [%0], {%1,%2,%3,%4,%5,%6,%7,%8};"
                 :: "l"(p), "f"(a.x), "f"(a.y), "f"(a.z), "f"(a.w),
                    "f"(b.x), "f"(b.y), "f"(b.z), "f"(b.w) : "memory");
}

// ------------------------------------------------- node precompute (3 gates)
// chunks of 32 nodes, G=2 rows/thread, 3 gates fully unrolled (R7 proven).
__global__ void __launch_bounds__(256, 2) k_nodepre(
    const float* __restrict__ nf, int N, int nChunks,
    const float* __restrict__ w1a, const float* __restrict__ w2a, const float* __restrict__ ba,
    const float* __restrict__ w1b, const float* __restrict__ w2b, const float* __restrict__ bb,
    const float* __restrict__ w1c, const float* __restrict__ w2c, const float* __restrict__ bc)
{
    __shared__ float4 s_w1t[3][RK][D4 + 1];
    __shared__ float4 s_w2[3][RK * D4];
    __shared__ float4 s_b[3][D4];
    __shared__ float4 s_x[32][D4 + 1];

    int tid = threadIdx.x;
    for (int i = tid; i < D * RK; i += 256) {
        int k = i >> 4, r = i & 15;
        ((float*)&s_w1t[0][r][k >> 2])[k & 3] = w1a[i];
        ((float*)&s_w1t[1][r][k >> 2])[k & 3] = w1b[i];
        ((float*)&s_w1t[2][r][k >> 2])[k & 3] = w1c[i];
        ((float*)s_w2[0])[i] = w2a[i];
        ((float*)s_w2[1])[i] = w2b[i];
        ((float*)s_w2[2])[i] = w2c[i];
    }
    if (tid < D) {
        ((float*)s_b[0])[tid] = ba[tid];
        ((float*)s_b[1])[tid] = bb[tid];
        ((float*)s_b[2])[tid] = bc[tid];
    }
    __syncthreads();

    int warp = tid >> 5, l = tid & 31;
    int row = tid >> 4, lane = tid & 15;
    int rA = 2 * row, rB = 2 * row + 1;
    size_t lim = (size_t)N * D4;
    size_t limS = (size_t)N * 32;
    float4 z = make_float4(0.f, 0.f, 0.f, 0.f);

    for (int c = blockIdx.x; c < nChunks; c += gridDim.x) {
        {   // fused zero of g_S with 256-bit stores (1024 float4 per chunk)
            size_t f0 = (size_t)c * 1024 + (size_t)tid * 2;
#pragma unroll
            for (int k = 0; k < 2; k++) {
                size_t idx = f0 + 512 * k;
                if (idx + 1 < limS) stg256(&g_S[idx], z, z);
            }
        }

        __syncwarp();
        {   // warp-local staging: warp w consumes rows 4w..4w+3 = pairs 32w..32w+31
            size_t pidx = (size_t)c * 256 + (size_t)warp * 32 + l;   // pair index
            size_t f = 2 * pidx;
            if (f + 1 >= lim) f = lim - 2;
            float4 va, vb;
            ldg256(&((const float4*)nf)[f], va, vb);
            int i0 = (int)(f - (size_t)c * 512);
            if (i0 < 0) i0 = 510;   // safety (cannot happen except last chunk clamp)
            s_x[i0 >> 4][i0 & 15] = va;
            s_x[(i0 + 1) >> 4][(i0 + 1) & 15] = vb;
        }
        __syncwarp();

        // stage 1: t for both rows, all 3 gates
        ull pA0 = 0, pA1 = 0, pA2 = 0, pB0 = 0, pB1 = 0, pB2 = 0;
#pragma unroll
        for (int k4 = 0; k4 < D4; k4++) {
            ulonglong2 xa = *(const ulonglong2*)&s_x[rA][k4];
            ulonglong2 xb = *(const ulonglong2*)&s_x[rB][k4];
            ulonglong2 w0 = *(const ulonglong2*)&s_w1t[0][lane][k4];
            ulonglong2 w1_ = *(const ulonglong2*)&s_w1t[1][lane][k4];
            ulonglong2 w2_ = *(const ulonglong2*)&s_w1t[2][lane][k4];
            pA0 = fma2(xa.x, w0.x, pA0);  pA0 = fma2(xa.y, w0.y, pA0);
            pA1 = fma2(xa.x, w1_.x, pA1); pA1 = fma2(xa.y, w1_.y, pA1);
            pA2 = fma2(xa.x, w2_.x, pA2); pA2 = fma2(xa.y, w2_.y, pA2);
            pB0 = fma2(xb.x, w0.x, pB0);  pB0 = fma2(xb.y, w0.y, pB0);
            pB1 = fma2(xb.x, w1_.x, pB1); pB1 = fma2(xb.y, w1_.y, pB1);
            pB2 = fma2(xb.x, w2_.x, pB2); pB2 = fma2(xb.y, w2_.y, pB2);
        }
        float tA0, tA1, tA2, tB0, tB1, tB2;
        { float a, b;
          upk2(pA0, a, b); tA0 = a + b; upk2(pA1, a, b); tA1 = a + b;
          upk2(pA2, a, b); tA2 = a + b;
          upk2(pB0, a, b); tB0 = a + b; upk2(pB1, a, b); tB1 = a + b;
          upk2(pB2, a, b); tB2 = a + b; }

        // stage 2: all 3 gates, both rows
        ulonglong2 b0 = *(const ulonglong2*)&s_b[0][lane];
        ulonglong2 b1 = *(const ulonglong2*)&s_b[1][lane];
        ulonglong2 b2 = *(const ulonglong2*)&s_b[2][lane];
        ull aA00 = b0.x, aA01 = b0.y, aB00 = b0.x, aB01 = b0.y;
        ull aA10 = b1.x, aA11 = b1.y, aB10 = b1.x, aB11 = b1.y;
        ull aA20 = b2.x, aA21 = b2.y, aB20 = b2.x, aB21 = b2.y;
#pragma unroll
        for (int r = 0; r < RK; r++) {
            ulonglong2 w0 = *(const ulonglong2*)&s_w2[0][r * D4 + lane];
            ulonglong2 w1_ = *(const ulonglong2*)&s_w2[1][r * D4 + lane];
            ulonglong2 w2_ = *(const ulonglong2*)&s_w2[2][r * D4 + lane];
            float uA0 = __shfl_sync(0xffffffffu, tA0, r, 16);
            float uA1 = __shfl_sync(0xffffffffu, tA1, r, 16);
            float uA2 = __shfl_sync(0xffffffffu, tA2, r, 16);
            float uB0 = __shfl_sync(0xffffffffu, tB0, r, 16);
            float uB1 = __shfl_sync(0xffffffffu, tB1, r, 16);
            float uB2 = __shfl_sync(0xffffffffu, tB2, r, 16);
            ull uA0p = pk2(uA0, uA0), uA1p = pk2(uA1, uA1), uA2p = pk2(uA2, uA2);
            ull uB0p = pk2(uB0, uB0), uB1p = pk2(uB1, uB1), uB2p = pk2(uB2, uB2);
            aA00 = fma2(uA0p, w0.x, aA00);  aA01 = fma2(uA0p, w0.y, aA01);
            aA10 = fma2(uA1p, w1_.x, aA10); aA11 = fma2(uA1p, w1_.y, aA11);
            aA20 = fma2(uA2p, w2_.x, aA20); aA21 = fma2(uA2p, w2_.y, aA21);
            aB00 = fma2(uB0p, w0.x, aB00);  aB01 = fma2(uB0p, w0.y, aB01);
            aB10 = fma2(uB1p, w1_.x, aB10); aB11 = fma2(uB1p, w1_.y, aB11);
            aB20 = fma2(uB2p, w2_.x, aB20); aB21 = fma2(uB2p, w2_.y, aB21);
        }

        int nA = c * 32 + rA;
        int nB = c * 32 + rB;
        if (nA < N) {
            float4 vs, vh;
            { float a, b; upk2(aA00, a, b); vs.x = a; vs.y = b;
              upk2(aA01, a, b); vs.z = a; vs.w = b;
              upk2(aA20, a, b); vh.x = a; vh.y = b;
              upk2(aA21, a, b); vh.z = a; vh.w = b; }
            stg256(&g_AS[(size_t)nA * 32 + 2 * lane], vs, vh);   // [Asrc, Abh]
            *(ulonglong2*)&g_Adst[(size_t)nA * D4 + lane] = make_ulonglong2(aA10, aA11);
        }
        if (nB < N) {
            float4 vs, vh;
            { float a, b; upk2(aB00, a, b); vs.x = a; vs.y = b;
              upk2(aB01, a, b); vs.z = a; vs.w = b;
              upk2(aB20, a, b); vh.x = a; vh.y = b;
              upk2(aB21, a, b); vh.z = a; vh.w = b; }
            stg256(&g_AS[(size_t)nB * 32 + 2 * lane], vs, vh);
            *(ulonglong2*)&g_Adst[(size_t)nB * D4 + lane] = make_ulonglong2(aB10, aB11);
        }
    }
}

// ------------------------------------------------------------------ edge pass
// chunks of 64 edges, G=4 edges/thread (R5/R6-proven). Asrc+Abh in one v8
// gather; Ss/Sh scatter to adjacent 16B (same 32B sector).
__global__ void __launch_bounds__(256, 2) k_edge(
    const float* __restrict__ ef, const int* __restrict__ src, const int* __restrict__ dst,
    const float* __restrict__ w1, const float* __restrict__ w2, const float* __restrict__ bias,
    const float* __restrict__ lng, const float* __restrict__ lnb,
    float* __restrict__ yout, int E, int nChunks)
{
    __shared__ float4 s_w1t[RK][D4 + 1];
    __shared__ float4 s_w2[RK * D4];
    __shared__ float4 s_b[D4], s_g[D4], s_lb[D4];
    __shared__ float4 s_x[64][D4 + 1];

    int tid = threadIdx.x;
    for (int i = tid; i < D * RK; i += 256) {
        int k = i >> 4, r = i & 15;
        ((float*)&s_w1t[r][k >> 2])[k & 3] = w1[i];
        ((float*)s_w2)[i] = w2[i];
    }
    if (tid < D) {
        ((float*)s_b)[tid]  = bias[tid];
        ((float*)s_g)[tid]  = lng[tid];
        ((float*)s_lb)[tid] = lnb[tid];
    }
    __syncthreads();

    int warp = tid >> 5, l = tid & 31;
    int row = tid >> 4, lane = tid & 15;
    size_t limE = (size_t)E;
    size_t lim4 = limE * D4;

    for (int c = blockIdx.x; c < nChunks; c += gridDim.x) {
        size_t e0 = (size_t)c * 64;

        __syncwarp();
        {   // warp-local staging with v8: warp w consumes rows {2w,2w+1}+16g,
            // i.e. pair indices 16*(w+8g)+(l&15), g=0..3; 2 v8 loads per lane.
#pragma unroll
            for (int k = 0; k < 2; k++) {
                int g = 2 * k + (l >> 4);
                int pidx = 16 * (warp + 8 * g) + (l & 15);    // in [0,512)
                size_t f = e0 * D4 + 2 * (size_t)pidx;
                if (f + 1 >= lim4) f = lim4 - 2;
                float4 va, vb;
                ldg256(&((const float4*)ef)[f], va, vb);
                int i0 = (int)(f - e0 * D4);
                if (i0 < 0 || i0 > 1022) i0 = 1022;
                s_x[i0 >> 4][i0 & 15] = va;
                s_x[(i0 + 1) >> 4][(i0 + 1) & 15] = vb;
            }
        }

        // indices + gathers early (L2 latency overlaps stage 1)
        int sj[4], dj[4];
#pragma unroll
        for (int j = 0; j < 4; j++) {
            size_t e = e0 + row + 16 * j;
            size_t ec = e < limE ? e : limE - 1;
            sj[j] = src[ec]; dj[j] = dst[ec];
        }
        // one v8 load per j: [Asrc, Abh]; plus 16B Adst
        float4 fs[4], fh[4];
        ulonglong2 gd[4];
#pragma unroll
        for (int j = 0; j < 4; j++) {
            ldg256(&g_AS[(size_t)sj[j] * 32 + 2 * lane], fs[j], fh[j]);
            gd[j] = *(const ulonglong2*)&g_Adst[(size_t)dj[j] * D4 + lane];
        }

        __syncwarp();

        // stage 1: t = xe @ w1
        ull p0 = 0, p1 = 0, p2 = 0, p3 = 0;
#pragma unroll
        for (int k4 = 0; k4 < D4; k4++) {
            ulonglong2 w = *(const ulonglong2*)&s_w1t[lane][k4];
            ulonglong2 x0 = *(const ulonglong2*)&s_x[row][k4];
            ulonglong2 x1 = *(const ulonglong2*)&s_x[row + 16][k4];
            ulonglong2 x2 = *(const ulonglong2*)&s_x[row + 32][k4];
            ulonglong2 x3 = *(const ulonglong2*)&s_x[row + 48][k4];
            p0 = fma2(x0.x, w.x, p0); p0 = fma2(x0.y, w.y, p0);
            p1 = fma2(x1.x, w.x, p1); p1 = fma2(x1.y, w.y, p1);
            p2 = fma2(x2.x, w.x, p2); p2 = fma2(x2.y, w.y, p2);
            p3 = fma2(x3.x, w.x, p3); p3 = fma2(x3.y, w.y, p3);
        }
        float t0, t1, t2, t3;
        { float a, b;
          upk2(p0, a, b); t0 = a + b; upk2(p1, a, b); t1 = a + b;
          upk2(p2, a, b); t2 = a + b; upk2(p3, a, b); t3 = a + b; }

        // fold gathers into accumulator INIT
        ulonglong2 bb2 = *(const ulonglong2*)&s_b[lane];
        ull gsx[4], gsy[4];
#pragma unroll
        for (int j = 0; j < 4; j++) {
            gsx[j] = pk2(fs[j].x, fs[j].y);
            gsy[j] = pk2(fs[j].z, fs[j].w);
        }
        ull a00 = add2(bb2.x, add2(gsx[0], gd[0].x));
        ull a01 = add2(bb2.y, add2(gsy[0], gd[0].y));
        ull a10 = add2(bb2.x, add2(gsx[1], gd[1].x));
        ull a11 = add2(bb2.y, add2(gsy[1], gd[1].y));
        ull a20 = add2(bb2.x, add2(gsx[2], gd[2].x));
        ull a21 = add2(bb2.y, add2(gsy[2], gd[2].y));
        ull a30 = add2(bb2.x, add2(gsx[3], gd[3].x));
        ull a31 = add2(bb2.y, add2(gsy[3], gd[3].y));

        // stage 2: acc += t @ w2
#pragma unroll
        for (int r = 0; r < RK; r++) {
            ulonglong2 w = *(const ulonglong2*)&s_w2[r * D4 + lane];
            float u0 = __shfl_sync(0xffffffffu, t0, r, 16);
            float u1 = __shfl_sync(0xffffffffu, t1, r, 16);
            float u2 = __shfl_sync(0xffffffffu, t2, r, 16);
            float u3 = __shfl_sync(0xffffffffu, t3, r, 16);
            ull u0p = pk2(u0, u0), u1p = pk2(u1, u1);
            ull u2p = pk2(u2, u2), u3p = pk2(u3, u3);
            a00 = fma2(u0p, w.x, a00); a01 = fma2(u0p, w.y, a01);
            a10 = fma2(u1p, w.x, a10); a11 = fma2(u1p, w.y, a11);
            a20 = fma2(u2p, w.x, a20); a21 = fma2(u2p, w.y, a21);
            a30 = fma2(u3p, w.x, a30); a31 = fma2(u3p, w.y, a31);
        }

        float4 gg = s_g[lane], lb = s_lb[lane];

#pragma unroll
        for (int j = 0; j < 4; j++) {
            ull acc0 = (j == 0) ? a00 : (j == 1) ? a10 : (j == 2) ? a20 : a30;
            ull acc1 = (j == 0) ? a01 : (j == 1) ? a11 : (j == 2) ? a21 : a31;

            float m0, m1, m2, m3;
            upk2(acc0, m0, m1); upk2(acc1, m2, m3);

            float g0 = sigm(m0), g1 = sigm(m1), g2 = sigm(m2), g3 = sigm(m3);

            size_t e = e0 + row + 16 * j;
            bool valid = e < limE;
            size_t doff = (size_t)dj[j] * 32 + 2 * lane;
            if (valid) {
                red_add_v4(&g_S[doff],     make_float4(g0, g1, g2, g3));        // Ss
                red_add_v4(&g_S[doff + 1], make_float4(fh[j].x * g0, fh[j].y * g1,
                                                       fh[j].z * g2, fh[j].w * g3)); // Sh
            }

            float sum = m0 + m1 + m2 + m3;
            float ssq = m0*m0 + m1*m1 + m2*m2 + m3*m3;
#pragma unroll
            for (int off = 8; off; off >>= 1) {
                sum += __shfl_xor_sync(0xffffffffu, sum, off);
                ssq += __shfl_xor_sync(0xffffffffu, ssq, off);
            }
            float mu = sum * (1.0f / D);
            float rstd = rsqrtf(fmaf(-mu, mu, ssq * (1.0f / D)) + 1e-5f);

            float4 xe = s_x[row + 16 * j][lane];
            float v0 = (m0 - mu) * rstd * gg.x + lb.x;
            float v1 = (m1 - mu) * rstd * gg.y + lb.y;
            float v2 = (m2 - mu) * rstd * gg.z + lb.z;
            float v3 = (m3 - mu) * rstd * gg.w + lb.w;
            float4 o = make_float4(v0 * sigm(v0) + xe.x, v1 * sigm(v1) + xe.y,
                                   v2 * sigm(v2) + xe.z, v3 * sigm(v3) + xe.w);
            if (valid) __stcs(&((float4*)yout)[e * D4 + lane], o);
        }
    }
}

// ------------------------------------------------------------- node update
// G=2 (R7-proven); reads interleaved g_S with one v8 load per row.
__global__ void __launch_bounds__(256, 2) k_nodeupd(
    const float* __restrict__ nf,
    const float* __restrict__ w1, const float* __restrict__ w2, const float* __restrict__ bias,
    const float* __restrict__ lng, const float* __restrict__ lnb,
    float* __restrict__ xout, int N, int nChunks)
{
    __shared__ float4 s_w1t[RK][D4 + 1];
    __shared__ float4 s_w2[RK * D4];
    __shared__ float4 s_b[D4], s_g[D4], s_lb[D4];
    __shared__ float4 s_x[32][D4 + 1];

    int tid = threadIdx.x;
    for (int i = tid; i < D * RK; i += 256) {
        int k = i >> 4, r = i & 15;
        ((float*)&s_w1t[r][k >> 2])[k & 3] = w1[i];
        ((float*)s_w2)[i] = w2[i];
    }
    if (tid < D) {
        ((float*)s_b)[tid]  = bias[tid];
        ((float*)s_g)[tid]  = lng[tid];
        ((float*)s_lb)[tid] = lnb[tid];
    }
    __syncthreads();

    int warp = tid >> 5, l = tid & 31;
    int row = tid >> 4, lane = tid & 15;
    int rA = 2 * row, rB = 2 * row + 1;
    size_t lim = (size_t)N * D4;

    for (int c = blockIdx.x; c < nChunks; c += gridDim.x) {
        __syncwarp();
        {   // warp-local v8 staging (warp w consumes rows 4w..4w+3)
            size_t pidx = (size_t)c * 256 + (size_t)warp * 32 + l;
            size_t f = 2 * pidx;
            if (f + 1 >= lim) f = lim - 2;
            float4 va, vb;
            ldg256(&((const float4*)nf)[f], va, vb);
            int i0 = (int)(f - (size_t)c * 512);
            if (i0 < 0) i0 = 510;
            s_x[i0 >> 4][i0 & 15] = va;
            s_x[(i0 + 1) >> 4][(i0 + 1) & 15] = vb;
        }

        int nA = c * 32 + rA;
        int nB = c * 32 + rB;
        int nAc = nA < N ? nA : N - 1;
        int nBc = nB < N ? nB : N - 1;
        float4 sdA, shA, sdB, shB;
        ldg256(&g_S[(size_t)nAc * 32 + 2 * lane], sdA, shA);   // [Ss, Sh]
        ldg256(&g_S[(size_t)nBc * 32 + 2 * lane], sdB, shB);

        __syncwarp();

        ull pA = 0, pB = 0;
#pragma unroll
        for (int k4 = 0; k4 < D4; k4++) {
            ulonglong2 w = *(const ulonglong2*)&s_w1t[lane][k4];
            ulonglong2 xa = *(const ulonglong2*)&s_x[rA][k4];
            ulonglong2 xb = *(const ulonglong2*)&s_x[rB][k4];
            pA = fma2(xa.x, w.x, pA); pA = fma2(xa.y, w.y, pA);
            pB = fma2(xb.x, w.x, pB); pB = fma2(xb.y, w.y, pB);
        }
        float tA, tB;
        { float a, b; upk2(pA, a, b); tA = a + b; upk2(pB, a, b); tB = a + b; }

        ulonglong2 bb2 = *(const ulonglong2*)&s_b[lane];
        ull accA0 = bb2.x, accA1 = bb2.y, accB0 = bb2.x, accB1 = bb2.y;
#pragma unroll
        for (int r = 0; r < RK; r++) {
            ulonglong2 w = *(const ulonglong2*)&s_w2[r * D4 + lane];
            float trA = __shfl_sync(0xffffffffu, tA, r, 16);
            float trB = __shfl_sync(0xffffffffu, tB, r, 16);
            ull ta = pk2(trA, trA), tb = pk2(trB, trB);
            accA0 = fma2(ta, w.x, accA0); accA1 = fma2(ta, w.y, accA1);
            accB0 = fma2(tb, w.x, accB0); accB1 = fma2(tb, w.y, accB1);
        }

        float4 gg = s_g[lane], lb = s_lb[lane];

#pragma unroll
        for (int half = 0; half < 2; half++) {
            ull acc0 = half ? accB0 : accA0;
            ull acc1 = half ? accB1 : accA1;
            float4 sd = half ? sdB : sdA;
            float4 sh = half ? shB : shA;
            int n = half ? nB : nA;
            int rr = half ? rB : rA;

            float m0, m1, m2, m3;
            upk2(acc0, m0, m1); upk2(acc1, m2, m3);
            m0 += sh.x * __fdividef(1.f, sd.x + 1e-6f);
            m1 += sh.y * __fdividef(1.f, sd.y + 1e-6f);
            m2 += sh.z * __fdividef(1.f, sd.z + 1e-6f);
            m3 += sh.w * __fdividef(1.f, sd.w + 1e-6f);

            float sum = m0 + m1 + m2 + m3;
            float ssq = m0*m0 + m1*m1 + m2*m2 + m3*m3;
#pragma unroll
            for (int off = 8; off; off >>= 1) {
                sum += __shfl_xor_sync(0xffffffffu, sum, off);
                ssq += __shfl_xor_sync(0xffffffffu, ssq, off);
            }
            float mu = sum * (1.0f / D);
            float rstd = rsqrtf(fmaf(-mu, mu, ssq * (1.0f / D)) + 1e-5f);

            float4 xn = s_x[rr][lane];
            float v0 = (m0 - mu) * rstd * gg.x + lb.x;
            float v1 = (m1 - mu) * rstd * gg.y + lb.y;
            float v2 = (m2 - mu) * rstd * gg.z + lb.z;
            float v3 = (m3 - mu) * rstd * gg.w + lb.w;
            float4 ov = make_float4(v0 * sigm(v0) + xn.x, v1 * sigm(v1) + xn.y,
                                    v2 * sigm(v2) + xn.z, v3 * sigm(v3) + xn.w);
            if (n < N) __stcs(&((float4*)xout)[(size_t)n * D4 + lane], ov);
        }
    }
}

// ---------------------------------------------------------------------- launch
extern "C" void kernel_launch(void* const* d_in, const int* in_sizes, int n_in,
                              void* d_out, int out_size)
{
    const float* nf  = (const float*)d_in[0];
    const float* ef  = (const float*)d_in[1];
    const int*   src = (const int*)d_in[2];
    const int*   dst = (const int*)d_in[3];
    const float* sgw1 = (const float*)d_in[4];
    const float* sgw2 = (const float*)d_in[5];
    const float* sgb  = (const float*)d_in[6];
    const float* dgw1 = (const float*)d_in[7];
    const float* dgw2 = (const float*)d_in[8];
    const float* dgb  = (const float*)d_in[9];
    const float* egw1 = (const float*)d_in[10];
    const float* egw2 = (const float*)d_in[11];
    const float* egb  = (const float*)d_in[12];
    const float* suw1 = (const float*)d_in[13];
    const float* suw2 = (const float*)d_in[14];
    const float* sub  = (const float*)d_in[15];
    const float* duw1 = (const float*)d_in[16];
    const float* duw2 = (const float*)d_in[17];
    const float* dub  = (const float*)d_in[18];
    const float* ln_n_g = (const float*)d_in[19];
    const float* ln_n_b = (const float*)d_in[20];
    const float* ln_e_g = (const float*)d_in[21];
    const float* ln_e_b = (const float*)d_in[22];

    int N = in_sizes[0] / D;
    int E = in_sizes[2];

    float* xout = (float*)d_out;
    float* yout = xout + (size_t)N * D;

    int ncN = (N + 31) / 32;
    int ncE = (E + 63) / 64;

    int gN = ncN < NBLK ? ncN : NBLK;
    int gE = ncE < NBLK ? ncE : NBLK;

    k_nodepre<<<gN, 256>>>(nf, N, ncN,
                           sgw1, sgw2, sgb,
                           dgw1, dgw2, dgb,
                           duw1, duw2, dub);
    k_edge<<<gE, 256>>>(ef, src, dst,
                        egw1, egw2, egb,
                        ln_e_g, ln_e_b, yout, E, ncE);
    k_nodeupd<<<gN, 256>>>(nf, suw1, suw2, sub,
                           ln_n_g, ln_n_b, xout, N, ncN);
}

// round 12
// speedup vs baseline: 1.1056x; 1.1056x over previous
#include <cuda_runtime.h>

#define D    64
#define D4   16
#define RK   16
#define MAXN 100000
#define NBLK 592

typedef unsigned long long ull;

// Scratch (allocation-free rule: __device__ globals). float4 for 16B alignment.
static __device__ float4 g_Asrc[(size_t)MAXN * D4];
static __device__ float4 g_Adst[(size_t)MAXN * D4];
static __device__ float4 g_Abh [(size_t)MAXN * D4];
static __device__ float4 g_Sh  [(size_t)MAXN * D4];
static __device__ float4 g_Ss  [(size_t)MAXN * D4];

// sigmoid via HW tanh: sigmoid(x) = 0.5*tanh(0.5x) + 0.5
__device__ __forceinline__ float sigm(float x) {
    float t;
    asm("tanh.approx.f32 %0, %1;" : "=f"(t) : "f"(0.5f * x));
    return fmaf(0.5f, t, 0.5f);
}
__device__ __forceinline__ void red_add_v4(float4* p, float4 v) {
    asm volatile("red.global.add.v4.f32 [%0], {%1,%2,%3,%4};"
                 :: "l"(p), "f"(v.x), "f"(v.y), "f"(v.z), "f"(v.w) : "memory");
}
// packed fp32x2 helpers (sm_100+)
__device__ __forceinline__ ull pk2(float lo, float hi) {
    ull r; asm("mov.b64 %0,{%1,%2};" : "=l"(r) : "f"(lo), "f"(hi)); return r;
}
__device__ __forceinline__ void upk2(ull v, float& lo, float& hi) {
    asm("mov.b64 {%0,%1},%2;" : "=f"(lo), "=f"(hi) : "l"(v));
}
__device__ __forceinline__ ull fma2(ull a, ull b, ull c) {
    ull d; asm("fma.rn.f32x2 %0,%1,%2,%3;" : "=l"(d) : "l"(a), "l"(b), "l"(c)); return d;
}
__device__ __forceinline__ ull add2(ull a, ull b) {
    ull d; asm("add.rn.f32x2 %0,%1,%2;" : "=l"(d) : "l"(a), "l"(b)); return d;
}

// ------------------------------------------------- node precompute (3 gates)
// R7 champion: chunks of 32 nodes, G=2 rows/thread, 3 gates fully unrolled.
__global__ void __launch_bounds__(256, 2) k_nodepre(
    const float* __restrict__ nf, int N, int nChunks,
    const float* __restrict__ w1a, const float* __restrict__ w2a, const float* __restrict__ ba,
    const float* __restrict__ w1b, const float* __restrict__ w2b, const float* __restrict__ bb,
    const float* __restrict__ w1c, const float* __restrict__ w2c, const float* __restrict__ bc)
{
    __shared__ float4 s_w1t[3][RK][D4 + 1];
    __shared__ float4 s_w2[3][RK * D4];
    __shared__ float4 s_b[3][D4];
    __shared__ float4 s_x[32][D4 + 1];

    int tid = threadIdx.x;
    for (int i = tid; i < D * RK; i += 256) {
        int k = i >> 4, r = i & 15;
        ((float*)&s_w1t[0][r][k >> 2])[k & 3] = w1a[i];
        ((float*)&s_w1t[1][r][k >> 2])[k & 3] = w1b[i];
        ((float*)&s_w1t[2][r][k >> 2])[k & 3] = w1c[i];
        ((float*)s_w2[0])[i] = w2a[i];
        ((float*)s_w2[1])[i] = w2b[i];
        ((float*)s_w2[2])[i] = w2c[i];
    }
    if (tid < D) {
        ((float*)s_b[0])[tid] = ba[tid];
        ((float*)s_b[1])[tid] = bb[tid];
        ((float*)s_b[2])[tid] = bc[tid];
    }
    __syncthreads();

    int warp = tid >> 5, l = tid & 31;
    int row = tid >> 4, lane = tid & 15;
    int rA = 2 * row, rB = 2 * row + 1;
    size_t lim = (size_t)N * D4;
    float4 z = make_float4(0.f, 0.f, 0.f, 0.f);

    for (int c = blockIdx.x; c < nChunks; c += gridDim.x) {
        {   // fused zero of Sh/Ss
            size_t i1 = (size_t)c * 512 + tid;
            size_t i2 = i1 + 256;
            if (i1 < lim) { g_Sh[i1] = z; g_Ss[i1] = z; }
            if (i2 < lim) { g_Sh[i2] = z; g_Ss[i2] = z; }
        }

        __syncwarp();
        {   // warp-local staging of this warp's 4 node rows
            size_t base = (size_t)c * 512 + (size_t)warp * 64;
            size_t i1 = base + l, i2 = base + 32 + l;
            float4 v1 = ((const float4*)nf)[i1 < lim ? i1 : lim - 1];
            float4 v2 = ((const float4*)nf)[i2 < lim ? i2 : lim - 1];
            s_x[warp * 4 + (l >> 4)][l & 15]     = v1;
            s_x[warp * 4 + 2 + (l >> 4)][l & 15] = v2;
        }
        __syncwarp();

        // stage 1: t for both rows, all 3 gates
        ull pA0 = 0, pA1 = 0, pA2 = 0, pB0 = 0, pB1 = 0, pB2 = 0;
#pragma unroll
        for (int k4 = 0; k4 < D4; k4++) {
            ulonglong2 xa = *(const ulonglong2*)&s_x[rA][k4];
            ulonglong2 xb = *(const ulonglong2*)&s_x[rB][k4];
            ulonglong2 w0 = *(const ulonglong2*)&s_w1t[0][lane][k4];
            ulonglong2 w1_ = *(const ulonglong2*)&s_w1t[1][lane][k4];
            ulonglong2 w2_ = *(const ulonglong2*)&s_w1t[2][lane][k4];
            pA0 = fma2(xa.x, w0.x, pA0);  pA0 = fma2(xa.y, w0.y, pA0);
            pA1 = fma2(xa.x, w1_.x, pA1); pA1 = fma2(xa.y, w1_.y, pA1);
            pA2 = fma2(xa.x, w2_.x, pA2); pA2 = fma2(xa.y, w2_.y, pA2);
            pB0 = fma2(xb.x, w0.x, pB0);  pB0 = fma2(xb.y, w0.y, pB0);
            pB1 = fma2(xb.x, w1_.x, pB1); pB1 = fma2(xb.y, w1_.y, pB1);
            pB2 = fma2(xb.x, w2_.x, pB2); pB2 = fma2(xb.y, w2_.y, pB2);
        }
        float tA0, tA1, tA2, tB0, tB1, tB2;
        { float a, b;
          upk2(pA0, a, b); tA0 = a + b; upk2(pA1, a, b); tA1 = a + b;
          upk2(pA2, a, b); tA2 = a + b;
          upk2(pB0, a, b); tB0 = a + b; upk2(pB1, a, b); tB1 = a + b;
          upk2(pB2, a, b); tB2 = a + b; }

        // stage 2: all 3 gates, both rows (12 ull accumulators live)
        ulonglong2 b0 = *(const ulonglong2*)&s_b[0][lane];
        ulonglong2 b1 = *(const ulonglong2*)&s_b[1][lane];
        ulonglong2 b2 = *(const ulonglong2*)&s_b[2][lane];
        ull aA00 = b0.x, aA01 = b0.y, aB00 = b0.x, aB01 = b0.y;
        ull aA10 = b1.x, aA11 = b1.y, aB10 = b1.x, aB11 = b1.y;
        ull aA20 = b2.x, aA21 = b2.y, aB20 = b2.x, aB21 = b2.y;
#pragma unroll
        for (int r = 0; r < RK; r++) {
            ulonglong2 w0 = *(const ulonglong2*)&s_w2[0][r * D4 + lane];
            ulonglong2 w1_ = *(const ulonglong2*)&s_w2[1][r * D4 + lane];
            ulonglong2 w2_ = *(const ulonglong2*)&s_w2[2][r * D4 + lane];
            float uA0 = __shfl_sync(0xffffffffu, tA0, r, 16);
            float uA1 = __shfl_sync(0xffffffffu, tA1, r, 16);
            float uA2 = __shfl_sync(0xffffffffu, tA2, r, 16);
            float uB0 = __shfl_sync(0xffffffffu, tB0, r, 16);
            float uB1 = __shfl_sync(0xffffffffu, tB1, r, 16);
            float uB2 = __shfl_sync(0xffffffffu, tB2, r, 16);
            ull uA0p = pk2(uA0, uA0), uA1p = pk2(uA1, uA1), uA2p = pk2(uA2, uA2);
            ull uB0p = pk2(uB0, uB0), uB1p = pk2(uB1, uB1), uB2p = pk2(uB2, uB2);
            aA00 = fma2(uA0p, w0.x, aA00);  aA01 = fma2(uA0p, w0.y, aA01);
            aA10 = fma2(uA1p, w1_.x, aA10); aA11 = fma2(uA1p, w1_.y, aA11);
            aA20 = fma2(uA2p, w2_.x, aA20); aA21 = fma2(uA2p, w2_.y, aA21);
            aB00 = fma2(uB0p, w0.x, aB00);  aB01 = fma2(uB0p, w0.y, aB01);
            aB10 = fma2(uB1p, w1_.x, aB10); aB11 = fma2(uB1p, w1_.y, aB11);
            aB20 = fma2(uB2p, w2_.x, aB20); aB21 = fma2(uB2p, w2_.y, aB21);
        }

        int nA = c * 32 + rA;
        int nB = c * 32 + rB;
        if (nA < N) {
            size_t o = (size_t)nA * D4 + lane;
            *(ulonglong2*)&g_Asrc[o] = make_ulonglong2(aA00, aA01);
            *(ulonglong2*)&g_Adst[o] = make_ulonglong2(aA10, aA11);
            *(ulonglong2*)&g_Abh [o] = make_ulonglong2(aA20, aA21);
        }
        if (nB < N) {
            size_t o = (size_t)nB * D4 + lane;
            *(ulonglong2*)&g_Asrc[o] = make_ulonglong2(aB00, aB01);
            *(ulonglong2*)&g_Adst[o] = make_ulonglong2(aB10, aB11);
            *(ulonglong2*)&g_Abh [o] = make_ulonglong2(aB20, aB21);
        }
    }
}

// ------------------------------------------------------------------ edge pass
// R5 champion structure: chunks of 64 edges, G=4 edges/thread, early gathers
// folded into acc-init, gh after stage-1.  NEW: next-chunk src/dst prefetch —
// gathers issue at loop top with zero dependent-load wait.
__global__ void __launch_bounds__(256, 2) k_edge(
    const float* __restrict__ ef, const int* __restrict__ src, const int* __restrict__ dst,
    const float* __restrict__ w1, const float* __restrict__ w2, const float* __restrict__ bias,
    const float* __restrict__ lng, const float* __restrict__ lnb,
    float* __restrict__ yout, int E, int nChunks)
{
    __shared__ float4 s_w1t[RK][D4 + 1];
    __shared__ float4 s_w2[RK * D4];
    __shared__ float4 s_b[D4], s_g[D4], s_lb[D4];
    __shared__ float4 s_x[64][D4 + 1];

    int tid = threadIdx.x;
    for (int i = tid; i < D * RK; i += 256) {
        int k = i >> 4, r = i & 15;
        ((float*)&s_w1t[r][k >> 2])[k & 3] = w1[i];
        ((float*)s_w2)[i] = w2[i];
    }
    if (tid < D) {
        ((float*)s_b)[tid]  = bias[tid];
        ((float*)s_g)[tid]  = lng[tid];
        ((float*)s_lb)[tid] = lnb[tid];
    }
    __syncthreads();

    int row = tid >> 4, lane = tid & 15;
    size_t limE = (size_t)E;
    size_t lim4 = limE * D4;

    // prefetch indices for the FIRST chunk
    int sj[4], dj[4];
    {
        size_t e0 = (size_t)blockIdx.x * 64;
#pragma unroll
        for (int j = 0; j < 4; j++) {
            size_t e = e0 + row + 16 * j;
            size_t ec = e < limE ? e : limE - 1;
            sj[j] = src[ec]; dj[j] = dst[ec];
        }
    }

    for (int c = blockIdx.x; c < nChunks; c += gridDim.x) {
        size_t e0 = (size_t)c * 64;
        size_t base = e0 * D4 + tid;

        // gathers issue IMMEDIATELY (indices already in registers)
        ulonglong2 gs[4], gd[4];
#pragma unroll
        for (int j = 0; j < 4; j++) {
            gs[j] = *(const ulonglong2*)&g_Asrc[(size_t)sj[j] * D4 + lane];
            gd[j] = *(const ulonglong2*)&g_Adst[(size_t)dj[j] * D4 + lane];
        }

        __syncwarp();
#pragma unroll
        for (int j = 0; j < 4; j++) {
            size_t idx = base + 256 * j;
            s_x[row + 16 * j][lane] = __ldcs(&((const float4*)ef)[idx < lim4 ? idx : lim4 - 1]);
        }

        // prefetch NEXT chunk's indices (latency hidden under compute below)
        int nsj[4], ndj[4];
        {
            long long nc = (long long)c + gridDim.x;
            size_t ne0 = (nc < nChunks) ? (size_t)nc * 64 : e0;
#pragma unroll
            for (int j = 0; j < 4; j++) {
                size_t e = ne0 + row + 16 * j;
                size_t ec = e < limE ? e : limE - 1;
                nsj[j] = src[ec]; ndj[j] = dst[ec];
            }
        }

        __syncwarp();

        // stage 1: t = xe @ w1
        ull p0 = 0, p1 = 0, p2 = 0, p3 = 0;
#pragma unroll
        for (int k4 = 0; k4 < D4; k4++) {
            ulonglong2 w = *(const ulonglong2*)&s_w1t[lane][k4];
            ulonglong2 x0 = *(const ulonglong2*)&s_x[row][k4];
            ulonglong2 x1 = *(const ulonglong2*)&s_x[row + 16][k4];
            ulonglong2 x2 = *(const ulonglong2*)&s_x[row + 32][k4];
            ulonglong2 x3 = *(const ulonglong2*)&s_x[row + 48][k4];
            p0 = fma2(x0.x, w.x, p0); p0 = fma2(x0.y, w.y, p0);
            p1 = fma2(x1.x, w.x, p1); p1 = fma2(x1.y, w.y, p1);
            p2 = fma2(x2.x, w.x, p2); p2 = fma2(x2.y, w.y, p2);
            p3 = fma2(x3.x, w.x, p3); p3 = fma2(x3.y, w.y, p3);
        }
        float t0, t1, t2, t3;
        { float a, b;
          upk2(p0, a, b); t0 = a + b; upk2(p1, a, b); t1 = a + b;
          upk2(p2, a, b); t2 = a + b; upk2(p3, a, b); t3 = a + b; }

        // fold gathers into accumulator INIT (frees gs/gd registers)
        ulonglong2 bb2 = *(const ulonglong2*)&s_b[lane];
        ull a00 = add2(bb2.x, add2(gs[0].x, gd[0].x));
        ull a01 = add2(bb2.y, add2(gs[0].y, gd[0].y));
        ull a10 = add2(bb2.x, add2(gs[1].x, gd[1].x));
        ull a11 = add2(bb2.y, add2(gs[1].y, gd[1].y));
        ull a20 = add2(bb2.x, add2(gs[2].x, gd[2].x));
        ull a21 = add2(bb2.y, add2(gs[2].y, gd[2].y));
        ull a30 = add2(bb2.x, add2(gs[3].x, gd[3].x));
        ull a31 = add2(bb2.y, add2(gs[3].y, gd[3].y));

        // prefetch Bh gathers (consumed in epilogue; hidden under stage 2)
        ulonglong2 gh[4];
#pragma unroll
        for (int j = 0; j < 4; j++)
            gh[j] = *(const ulonglong2*)&g_Abh[(size_t)sj[j] * D4 + lane];

        // stage 2: acc += t @ w2
#pragma unroll
        for (int r = 0; r < RK; r++) {
            ulonglong2 w = *(const ulonglong2*)&s_w2[r * D4 + lane];
            float u0 = __shfl_sync(0xffffffffu, t0, r, 16);
            float u1 = __shfl_sync(0xffffffffu, t1, r, 16);
            float u2 = __shfl_sync(0xffffffffu, t2, r, 16);
            float u3 = __shfl_sync(0xffffffffu, t3, r, 16);
            ull u0p = pk2(u0, u0), u1p = pk2(u1, u1);
            ull u2p = pk2(u2, u2), u3p = pk2(u3, u3);
            a00 = fma2(u0p, w.x, a00); a01 = fma2(u0p, w.y, a01);
            a10 = fma2(u1p, w.x, a10); a11 = fma2(u1p, w.y, a11);
            a20 = fma2(u2p, w.x, a20); a21 = fma2(u2p, w.y, a21);
            a30 = fma2(u3p, w.x, a30); a31 = fma2(u3p, w.y, a31);
        }

        float4 gg = s_g[lane], lb = s_lb[lane];

#pragma unroll
        for (int j = 0; j < 4; j++) {
            ull acc0 = (j == 0) ? a00 : (j == 1) ? a10 : (j == 2) ? a20 : a30;
            ull acc1 = (j == 0) ? a01 : (j == 1) ? a11 : (j == 2) ? a21 : a31;

            float m0, m1, m2, m3;
            upk2(acc0, m0, m1); upk2(acc1, m2, m3);

            float g0 = sigm(m0), g1 = sigm(m1), g2 = sigm(m2), g3 = sigm(m3);

            size_t e = e0 + row + 16 * j;
            bool valid = e < limE;
            size_t doff = (size_t)dj[j] * D4 + lane;
            if (valid) {
                float h0, h1, h2, h3;
                upk2(gh[j].x, h0, h1); upk2(gh[j].y, h2, h3);
                red_add_v4(&g_Ss[doff], make_float4(g0, g1, g2, g3));
                red_add_v4(&g_Sh[doff], make_float4(h0 * g0, h1 * g1, h2 * g2, h3 * g3));
            }

            float sum = m0 + m1 + m2 + m3;
            float ssq = m0*m0 + m1*m1 + m2*m2 + m3*m3;
#pragma unroll
            for (int off = 8; off; off >>= 1) {
                sum += __shfl_xor_sync(0xffffffffu, sum, off);
                ssq += __shfl_xor_sync(0xffffffffu, ssq, off);
            }
            float mu = sum * (1.0f / D);
            float rstd = rsqrtf(fmaf(-mu, mu, ssq * (1.0f / D)) + 1e-5f);

            float4 xe = s_x[row + 16 * j][lane];
            float v0 = (m0 - mu) * rstd * gg.x + lb.x;
            float v1 = (m1 - mu) * rstd * gg.y + lb.y;
            float v2 = (m2 - mu) * rstd * gg.z + lb.z;
            float v3 = (m3 - mu) * rstd * gg.w + lb.w;
            float4 o = make_float4(v0 * sigm(v0) + xe.x, v1 * sigm(v1) + xe.y,
                                   v2 * sigm(v2) + xe.z, v3 * sigm(v3) + xe.w);
            if (valid) __stcs(&((float4*)yout)[e * D4 + lane], o);
        }

        // rotate prefetched indices
#pragma unroll
        for (int j = 0; j < 4; j++) { sj[j] = nsj[j]; dj[j] = ndj[j]; }
    }
}

// ------------------------------------------------------------- node update
// R7 champion: G=2.
__global__ void __launch_bounds__(256, 2) k_nodeupd(
    const float* __restrict__ nf,
    const float* __restrict__ w1, const float* __restrict__ w2, const float* __restrict__ bias,
    const float* __restrict__ lng, const float* __restrict__ lnb,
    float* __restrict__ xout, int N, int nChunks)
{
    __shared__ float4 s_w1t[RK][D4 + 1];
    __shared__ float4 s_w2[RK * D4];
    __shared__ float4 s_b[D4], s_g[D4], s_lb[D4];
    __shared__ float4 s_x[32][D4 + 1];

    int tid = threadIdx.x;
    for (int i = tid; i < D * RK; i += 256) {
        int k = i >> 4, r = i & 15;
        ((float*)&s_w1t[r][k >> 2])[k & 3] = w1[i];
        ((float*)s_w2)[i] = w2[i];
    }
    if (tid < D) {
        ((float*)s_b)[tid]  = bias[tid];
        ((float*)s_g)[tid]  = lng[tid];
        ((float*)s_lb)[tid] = lnb[tid];
    }
    __syncthreads();

    int warp = tid >> 5, l = tid & 31;
    int row = tid >> 4, lane = tid & 15;
    int rA = 2 * row, rB = 2 * row + 1;
    size_t lim = (size_t)N * D4;

    for (int c = blockIdx.x; c < nChunks; c += gridDim.x) {
        __syncwarp();
        {
            size_t base = (size_t)c * 512 + (size_t)warp * 64;
            size_t i1 = base + l, i2 = base + 32 + l;
            float4 v1 = ((const float4*)nf)[i1 < lim ? i1 : lim - 1];
            float4 v2 = ((const float4*)nf)[i2 < lim ? i2 : lim - 1];
            s_x[warp * 4 + (l >> 4)][l & 15]     = v1;
            s_x[warp * 4 + 2 + (l >> 4)][l & 15] = v2;
        }

        int nA = c * 32 + rA;
        int nB = c * 32 + rB;
        int nAc = nA < N ? nA : N - 1;
        int nBc = nB < N ? nB : N - 1;
        size_t oA = (size_t)nAc * D4 + lane;
        size_t oB = (size_t)nBc * D4 + lane;
        ulonglong2 hnA = *(const ulonglong2*)&g_Sh[oA];
        ulonglong2 hdA = *(const ulonglong2*)&g_Ss[oA];
        ulonglong2 hnB = *(const ulonglong2*)&g_Sh[oB];
        ulonglong2 hdB = *(const ulonglong2*)&g_Ss[oB];

        __syncwarp();

        ull pA = 0, pB = 0;
#pragma unroll
        for (int k4 = 0; k4 < D4; k4++) {
            ulonglong2 w = *(const ulonglong2*)&s_w1t[lane][k4];
            ulonglong2 xa = *(const ulonglong2*)&s_x[rA][k4];
            ulonglong2 xb = *(const ulonglong2*)&s_x[rB][k4];
            pA = fma2(xa.x, w.x, pA); pA = fma2(xa.y, w.y, pA);
            pB = fma2(xb.x, w.x, pB); pB = fma2(xb.y, w.y, pB);
        }
        float tA, tB;
        { float a, b; upk2(pA, a, b); tA = a + b; upk2(pB, a, b); tB = a + b; }

        ulonglong2 bb2 = *(const ulonglong2*)&s_b[lane];
        ull accA0 = bb2.x, accA1 = bb2.y, accB0 = bb2.x, accB1 = bb2.y;
#pragma unroll
        for (int r = 0; r < RK; r++) {
            ulonglong2 w = *(const ulonglong2*)&s_w2[r * D4 + lane];
            float trA = __shfl_sync(0xffffffffu, tA, r, 16);
            float trB = __shfl_sync(0xffffffffu, tB, r, 16);
            ull ta = pk2(trA, trA), tb = pk2(trB, trB);
            accA0 = fma2(ta, w.x, accA0); accA1 = fma2(ta, w.y, accA1);
            accB0 = fma2(tb, w.x, accB0); accB1 = fma2(tb, w.y, accB1);
        }

        float4 gg = s_g[lane], lb = s_lb[lane];

#pragma unroll
        for (int half = 0; half < 2; half++) {
            ull acc0 = half ? accB0 : accA0;
            ull acc1 = half ? accB1 : accA1;
            ulonglong2 hn = half ? hnB : hnA;
            ulonglong2 hd = half ? hdB : hdA;
            int n = half ? nB : nA;
            int rr = half ? rB : rA;

            float m0, m1, m2, m3, q0, q1, q2, q3, d0, d1, d2, d3;
            upk2(acc0, m0, m1); upk2(acc1, m2, m3);
            upk2(hn.x, q0, q1); upk2(hn.y, q2, q3);
            upk2(hd.x, d0, d1); upk2(hd.y, d2, d3);
            m0 += q0 * __fdividef(1.f, d0 + 1e-6f);
            m1 += q1 * __fdividef(1.f, d1 + 1e-6f);
            m2 += q2 * __fdividef(1.f, d2 + 1e-6f);
            m3 += q3 * __fdividef(1.f, d3 + 1e-6f);

            float sum = m0 + m1 + m2 + m3;
            float ssq = m0*m0 + m1*m1 + m2*m2 + m3*m3;
#pragma unroll
            for (int off = 8; off; off >>= 1) {
                sum += __shfl_xor_sync(0xffffffffu, sum, off);
                ssq += __shfl_xor_sync(0xffffffffu, ssq, off);
            }
            float mu = sum * (1.0f / D);
            float rstd = rsqrtf(fmaf(-mu, mu, ssq * (1.0f / D)) + 1e-5f);

            float4 xn = s_x[rr][lane];
            float v0 = (m0 - mu) * rstd * gg.x + lb.x;
            float v1 = (m1 - mu) * rstd * gg.y + lb.y;
            float v2 = (m2 - mu) * rstd * gg.z + lb.z;
            float v3 = (m3 - mu) * rstd * gg.w + lb.w;
            float4 ov = make_float4(v0 * sigm(v0) + xn.x, v1 * sigm(v1) + xn.y,
                                    v2 * sigm(v2) + xn.z, v3 * sigm(v3) + xn.w);
            if (n < N) __stcs(&((float4*)xout)[(size_t)n * D4 + lane], ov);
        }
    }
}

// ---------------------------------------------------------------------- launch
extern "C" void kernel_launch(void* const* d_in, const int* in_sizes, int n_in,
                              void* d_out, int out_size)
{
    const float* nf  = (const float*)d_in[0];
    const float* ef  = (const float*)d_in[1];
    const int*   src = (const int*)d_in[2];
    const int*   dst = (const int*)d_in[3];
    const float* sgw1 = (const float*)d_in[4];
    const float* sgw2 = (const float*)d_in[5];
    const float* sgb  = (const float*)d_in[6];
    const float* dgw1 = (const float*)d_in[7];
    const float* dgw2 = (const float*)d_in[8];
    const float* dgb  = (const float*)d_in[9];
    const float* egw1 = (const float*)d_in[10];
    const float* egw2 = (const float*)d_in[11];
    const float* egb  = (const float*)d_in[12];
    const float* suw1 = (const float*)d_in[13];
    const float* suw2 = (const float*)d_in[14];
    const float* sub  = (const float*)d_in[15];
    const float* duw1 = (const float*)d_in[16];
    const float* duw2 = (const float*)d_in[17];
    const float* dub  = (const float*)d_in[18];
    const float* ln_n_g = (const float*)d_in[19];
    const float* ln_n_b = (const float*)d_in[20];
    const float* ln_e_g = (const float*)d_in[21];
    const float* ln_e_b = (const float*)d_in[22];

    int N = in_sizes[0] / D;
    int E = in_sizes[2];

    float* xout = (float*)d_out;
    float* yout = xout + (size_t)N * D;

    int ncN = (N + 31) / 32;
    int ncE = (E + 63) / 64;

    int gN = ncN < NBLK ? ncN : NBLK;
    int gE = ncE < NBLK ? ncE : NBLK;

    k_nodepre<<<gN, 256>>>(nf, N, ncN,
                           sgw1, sgw2, sgb,
                           dgw1, dgw2, dgb,
                           duw1, duw2, dub);
    k_edge<<<gE, 256>>>(ef, src, dst,
                        egw1, egw2, egb,
                        ln_e_g, ln_e_b, yout, E, ncE);
    k_nodeupd<<<gN, 256>>>(nf, suw1, suw2, sub,
                           ln_n_g, ln_n_b, xout, N, ncN);
}